// round 11
// baseline (speedup 1.0000x reference)
#include <cuda_runtime.h>

#define BATCH 16
#define CIN   512
#define MID   128
#define GRP   4
#define H     56
#define W     56
#define HW    (H*W)
#define MH    7
#define MW    7
#define EPSV  1e-5f

typedef unsigned long long ull;

__device__ __forceinline__ ull fma2(ull a, ull b, ull c) {
    ull d;
    asm("fma.rn.f32x2 %0, %1, %2, %3;" : "=l"(d) : "l"(a), "l"(b), "l"(c));
    return d;
}
__device__ __forceinline__ ull dup2(float v) {
    ull d;
    asm("mov.b64 %0, {%1, %1};" : "=l"(d) : "f"(v));
    return d;
}
__device__ __forceinline__ void unpack2(ull p, float& lo, float& hi) {
    asm("mov.b64 {%0, %1}, %2;" : "=f"(lo), "=f"(hi) : "l"(p));
}

// Scratch (device globals, no alloc).
__device__ float g_y1[BATCH * MID * HW];   // relu(bn1(conv1(x*m))) * m
// Pre-transposed weights:
__device__ float tw1[4 * 128 * 32];        // [g][ic][oc]
__device__ float tw2[4 * 32 * 9 * 32];     // [g][ic][tap][oc]
__device__ float tw3[4 * 32 * 128];        // [g][ic][oc]

__global__ void setup_tw(const float* __restrict__ w1,
                         const float* __restrict__ w2,
                         const float* __restrict__ w3)
{
    int i = blockIdx.x * 256 + threadIdx.x;
    if (i < 16384) {                       // tw1[g][ic][oc32]
        int g = i >> 12, r = i & 4095, ic = r >> 5, oc = r & 31;
        tw1[i] = w1[(g * 32 + oc) * 128 + ic];
    }
    if (i < 36864) {                       // tw2[g][ic][kk][oc32]
        int g = i / 9216, r = i % 9216, ic = r / 288, r2 = r % 288;
        int kk = r2 >> 5, oc = r2 & 31;
        tw2[i] = w2[(g * 32 + oc) * 288 + ic * 9 + kk];
    }
    if (i < 16384) {                       // tw3[g][ic][oc128]
        int g = i >> 12, r = i & 4095, ic = r >> 7, oc = r & 127;
        tw3[i] = w3[(g * 128 + oc) * 32 + ic];
    }
}

// ---------------------------------------------------------------------------
// Kernel 1: 1x1 grouped conv (512->128) + BN + ReLU (+mask), 8x8 tile.
// CTA = (tile, group-pair, batch), 256 thr. Thread = 4px x 4oc. f32x2.
// (unchanged from R10 — measured component)
// ---------------------------------------------------------------------------
__global__ __launch_bounds__(256, 3) void k1_conv1(
    const float* __restrict__ x, const float* __restrict__ mask,
    const float* __restrict__ g1, const float* __restrict__ b1,
    const float* __restrict__ m1, const float* __restrict__ v1)
{
    const int bh = blockIdx.x / 7, bw = blockIdx.x % 7;
    const int gp = blockIdx.y, b = blockIdx.z;      // group pair (0/1)
    const int h0 = bh * 8, w0 = bw * 8;
    const int t = threadIdx.x;
    const int ocq = t >> 4;            // [0,16): 4-oc slice within 64 oc
    const int pxq = t & 15;            // [0,16): 4-px quad
    const int r = pxq >> 1, cst = (pxq & 1) * 4;

    const float m0 = mask[((b * GRP + gp * 2 + 0) * MH + bh) * MW + bw];
    const float m1v = mask[((b * GRP + gp * 2 + 1) * MH + bh) * MW + bw];

    if (m0 == 0.0f && m1v == 0.0f) {
        const float4 z = make_float4(0.f, 0.f, 0.f, 0.f);
        #pragma unroll
        for (int k = 0; k < 4; k++) {
            int gc = gp * 64 + ocq * 4 + k;
            *(float4*)&g_y1[((b * MID + gc) * H + h0 + r) * W + w0 + cst] = z;
        }
        return;
    }

    __shared__ float  w_s[128][68];     // [ic][oc 0..63], pad 68
    __shared__ float4 x_s[2][32][16];   // [grp][ic-in-chunk][pxq]
    float4* xlin = &x_s[0][0][0];       // linear: idx == loader id

    {
        const float4* src = (const float4*)(tw1 + gp * 2 * 4096);
        float4* dst = (float4*)&w_s[0][0];          // row stride 17 float4
        #pragma unroll
        for (int j = 0; j < 8; j++) {
            int i = t + j * 256;
            int gg = i >> 10, rem = i & 1023;
            int ic = rem >> 3, oc4 = rem & 7;
            dst[ic * 17 + gg * 8 + oc4] = src[i];
        }
    }

    const int myg = ocq >> 3;               // warp-uniform group
    const bool active = (myg ? m1v : m0) != 0.0f;

    const float* xbase = x + (long)(b * CIN + gp * 2 * 128) * HW;
    long off[4];
    unsigned lmask = 0;
    #pragma unroll
    for (int j = 0; j < 4; j++) {
        int id = t + j * 256;
        int gg = id >> 9, ic = (id >> 4) & 31, p4 = id & 15;
        int rr = p4 >> 1, c2 = (p4 & 1) * 4;
        off[j] = ((long)(gg * 128 + ic) * H + h0 + rr) * W + w0 + c2;
        if ((gg ? m1v : m0) != 0.0f) lmask |= (1u << j);
    }

    #pragma unroll
    for (int j = 0; j < 4; j++) {
        float4 v = make_float4(0.f, 0.f, 0.f, 0.f);
        if (lmask & (1u << j)) v = *(const float4*)(xbase + off[j]);
        xlin[t + j * 256] = v;
    }
    __syncthreads();

    ull acc[4][2];
    #pragma unroll
    for (int k = 0; k < 4; k++) { acc[k][0] = 0ull; acc[k][1] = 0ull; }

    for (int cc = 0; cc < 4; cc++) {        // 4 chunks of 32 ic
        float4 pre[4];
        if (cc < 3) {
            #pragma unroll
            for (int j = 0; j < 4; j++) {
                pre[j] = make_float4(0.f, 0.f, 0.f, 0.f);
                if (lmask & (1u << j))
                    pre[j] = *(const float4*)(xbase + off[j] + (long)(cc + 1) * 32 * HW);
            }
        }
        if (active) {
            #pragma unroll
            for (int icc = 0; icc < 32; icc++) {
                ulonglong2 xp = *(const ulonglong2*)&x_s[myg][icc][pxq];
                float4 wv = *(const float4*)&w_s[cc * 32 + icc][ocq * 4];
                ull wd;
                wd = dup2(wv.x); acc[0][0] = fma2(wd, xp.x, acc[0][0]); acc[0][1] = fma2(wd, xp.y, acc[0][1]);
                wd = dup2(wv.y); acc[1][0] = fma2(wd, xp.x, acc[1][0]); acc[1][1] = fma2(wd, xp.y, acc[1][1]);
                wd = dup2(wv.z); acc[2][0] = fma2(wd, xp.x, acc[2][0]); acc[2][1] = fma2(wd, xp.y, acc[2][1]);
                wd = dup2(wv.w); acc[3][0] = fma2(wd, xp.x, acc[3][0]); acc[3][1] = fma2(wd, xp.y, acc[3][1]);
            }
        }
        if (cc < 3) {
            __syncthreads();
            #pragma unroll
            for (int j = 0; j < 4; j++)
                xlin[t + j * 256] = pre[j];
            __syncthreads();
        }
    }

    const float mymask = myg ? m1v : m0;
    #pragma unroll
    for (int k = 0; k < 4; k++) {
        int gc = gp * 64 + ocq * 4 + k;
        float sc = g1[gc] * rsqrtf(v1[gc] + EPSV);
        float bi = b1[gc] - m1[gc] * sc;
        float4 v = make_float4(0.f, 0.f, 0.f, 0.f);
        if (mymask != 0.0f) {
            float a0, a1, a2, a3;
            unpack2(acc[k][0], a0, a1);
            unpack2(acc[k][1], a2, a3);
            v.x = fmaxf(a0 * sc + bi, 0.0f);
            v.y = fmaxf(a1 * sc + bi, 0.0f);
            v.z = fmaxf(a2 * sc + bi, 0.0f);
            v.w = fmaxf(a3 * sc + bi, 0.0f);
        }
        *(float4*)&g_y1[((b * MID + gc) * H + h0 + r) * W + w0 + cst] = v;
    }
}

// ---------------------------------------------------------------------------
// Fused Kernel 2+3, 128 threads, thread = 4px x 4oc (conv2) / 4px x 8oc x 2
// halves (conv3). f32x2 throughout. Region B time-shared: w2 ph0 -> w2 ph1 ->
// w3. smem 33.8 KB -> 5-6 CTA/SM.
// smem (floats): A = [0,3840): halo [32][120 pad12]; later y2 [32][64]
//                B = [3840,8448): w2 slab [16][9][32] / w3 [32][128]
// ---------------------------------------------------------------------------
#define SM_A 0
#define SM_B 3840
#define K23_SMEM (8448 * 4)

__global__ __launch_bounds__(128) void k23_fused(
    const float* __restrict__ x, const float* __restrict__ mask,
    const float* __restrict__ g2, const float* __restrict__ b2,
    const float* __restrict__ m2, const float* __restrict__ v2,
    const float* __restrict__ g3, const float* __restrict__ b3,
    const float* __restrict__ m3, const float* __restrict__ v3,
    float* __restrict__ out)
{
    const int bh = blockIdx.x / 7, bw = blockIdx.x % 7;
    const int g = blockIdx.y, b = blockIdx.z;
    const int h0 = bh * 8, w0 = bw * 8;
    const int t = threadIdx.x;
    const int pxq = t >> 3;                 // [0,16): 4-px quad
    const int ocq = t & 7;                  // [0,8)
    const int r = pxq >> 1, cst = (pxq & 1) * 4;

    const float m = mask[((b * GRP + g) * MH + bh) * MW + bw];

    if (m == 0.0f) {
        // out = relu(bias3 + x): 2048 float4 / 128 thr = 16 each
        #pragma unroll
        for (int j = 0; j < 16; j++) {
            int id = t + j * 128;
            int oc = id >> 4, p4 = id & 15;
            int rr = p4 >> 1, c2 = (p4 & 1) * 4;
            int gc = g * 128 + oc;
            float sc = g3[gc] * rsqrtf(v3[gc] + EPSV);
            float bi = b3[gc] - m3[gc] * sc;
            long idx = ((long)(b * CIN + gc) * H + h0 + rr) * W + w0 + c2;
            float4 xv = *(const float4*)&x[idx];
            float4 v;
            v.x = fmaxf(bi + xv.x, 0.0f);
            v.y = fmaxf(bi + xv.y, 0.0f);
            v.z = fmaxf(bi + xv.z, 0.0f);
            v.w = fmaxf(bi + xv.w, 0.0f);
            *(float4*)&out[idx] = v;
        }
        return;
    }

    extern __shared__ float sm[];

    // halo: 32 ic x 10x10, row stride 12 (y1 post-mask; zero borders)
    for (int i = t; i < 32 * 100; i += 128) {
        int ic = i / 100, p = i % 100;
        int pr = p / 10, pc = p % 10;
        int rr = h0 + pr - 1, c2 = w0 + pc - 1;
        float v = 0.0f;
        if (rr >= 0 && rr < H && c2 >= 0 && c2 < W)
            v = g_y1[((b * MID + g * 32 + ic) * H + rr) * W + c2];
        sm[SM_A + ic * 120 + pr * 12 + pc] = v;
    }
    // w2 phase 0
    {
        const float4* src = (const float4*)(tw2 + g * 9216);
        float4* dst = (float4*)(sm + SM_B);
        #pragma unroll
        for (int j = 0; j < 9; j++) {
            int i = t + j * 128;
            if (i < 1152) dst[i] = src[i];
        }
    }
    __syncthreads();

    // ---- conv2: thread = 4 px x 4 oc (2 oc-pairs) ----
    ull acc2p[2][4];                        // [pair][px]
    #pragma unroll
    for (int p = 0; p < 2; p++)
        #pragma unroll
        for (int q = 0; q < 4; q++) acc2p[p][q] = 0ull;

    for (int ph = 0; ph < 2; ph++) {
        if (ph) {
            __syncthreads();
            const float4* src = (const float4*)(tw2 + g * 9216 + 4608);
            float4* dst = (float4*)(sm + SM_B);
            #pragma unroll
            for (int j = 0; j < 9; j++) {
                int i = t + j * 128;
                if (i < 1152) dst[i] = src[i];
            }
            __syncthreads();
        }
        #pragma unroll 4
        for (int icc = 0; icc < 16; icc++) {
            int ic = ph * 16 + icc;
            const float* hb = sm + SM_A + ic * 120;
            const float* wb = sm + SM_B + icc * 288;
            #pragma unroll
            for (int kr = 0; kr < 3; kr++) {
                float4 a = *(const float4*)&hb[(r + kr) * 12 + cst];
                float2 bq = *(const float2*)&hb[(r + kr) * 12 + cst + 4];
                ull xd[6];
                xd[0] = dup2(a.x); xd[1] = dup2(a.y); xd[2] = dup2(a.z);
                xd[3] = dup2(a.w); xd[4] = dup2(bq.x); xd[5] = dup2(bq.y);
                #pragma unroll
                for (int kc = 0; kc < 3; kc++) {
                    ulonglong2 wv = *(const ulonglong2*)&wb[(kr * 3 + kc) * 32 + ocq * 4];
                    #pragma unroll
                    for (int q = 0; q < 4; q++) {
                        acc2p[0][q] = fma2(wv.x, xd[kc + q], acc2p[0][q]);
                        acc2p[1][q] = fma2(wv.y, xd[kc + q], acc2p[1][q]);
                    }
                }
            }
        }
    }

    // all reads of halo (A) and w2 (B) done
    __syncthreads();

    // y2 -> region A [32 oc][64 px]; w3 -> region B
    #pragma unroll
    for (int p = 0; p < 2; p++) {
        float e0[4], e1[4];
        #pragma unroll
        for (int q = 0; q < 4; q++) unpack2(acc2p[p][q], e0[q], e1[q]);
        #pragma unroll
        for (int k = 0; k < 2; k++) {
            int oc = ocq * 4 + p * 2 + k;
            int gc = g * 32 + oc;
            float sc = g2[gc] * rsqrtf(v2[gc] + EPSV);
            float bi = b2[gc] - m2[gc] * sc;
            const float* av = k ? e1 : e0;
            float4 v;
            v.x = fmaxf(av[0] * sc + bi, 0.0f);
            v.y = fmaxf(av[1] * sc + bi, 0.0f);
            v.z = fmaxf(av[2] * sc + bi, 0.0f);
            v.w = fmaxf(av[3] * sc + bi, 0.0f);
            *(float4*)&sm[SM_A + oc * 64 + pxq * 4] = v;
        }
    }
    {
        const float4* src = (const float4*)(tw3 + g * 4096);
        float4* dst = (float4*)(sm + SM_B);
        #pragma unroll
        for (int j = 0; j < 8; j++)
            dst[t + j * 128] = src[t + j * 128];
    }
    __syncthreads();

    // ---- conv3: 2 halves of (4 px x 8 oc) ----
    const float* w3s = sm + SM_B;
    #pragma unroll
    for (int half = 0; half < 2; half++) {
        ull acc3p[4][4];                    // [ocpair][px]
        #pragma unroll
        for (int p = 0; p < 4; p++)
            #pragma unroll
            for (int q = 0; q < 4; q++) acc3p[p][q] = 0ull;

        const int ocb = half * 64 + ocq * 8;
        #pragma unroll 4
        for (int ic = 0; ic < 32; ic++) {
            float4 xv = *(const float4*)&sm[SM_A + ic * 64 + pxq * 4];
            ull xd0 = dup2(xv.x), xd1 = dup2(xv.y), xd2 = dup2(xv.z), xd3 = dup2(xv.w);
            const float* wr = &w3s[ic * 128 + ocb];
            ulonglong2 wa = *(const ulonglong2*)wr;
            ulonglong2 wb2 = *(const ulonglong2*)(wr + 4);
            acc3p[0][0] = fma2(wa.x, xd0, acc3p[0][0]);
            acc3p[0][1] = fma2(wa.x, xd1, acc3p[0][1]);
            acc3p[0][2] = fma2(wa.x, xd2, acc3p[0][2]);
            acc3p[0][3] = fma2(wa.x, xd3, acc3p[0][3]);
            acc3p[1][0] = fma2(wa.y, xd0, acc3p[1][0]);
            acc3p[1][1] = fma2(wa.y, xd1, acc3p[1][1]);
            acc3p[1][2] = fma2(wa.y, xd2, acc3p[1][2]);
            acc3p[1][3] = fma2(wa.y, xd3, acc3p[1][3]);
            acc3p[2][0] = fma2(wb2.x, xd0, acc3p[2][0]);
            acc3p[2][1] = fma2(wb2.x, xd1, acc3p[2][1]);
            acc3p[2][2] = fma2(wb2.x, xd2, acc3p[2][2]);
            acc3p[2][3] = fma2(wb2.x, xd3, acc3p[2][3]);
            acc3p[3][0] = fma2(wb2.y, xd0, acc3p[3][0]);
            acc3p[3][1] = fma2(wb2.y, xd1, acc3p[3][1]);
            acc3p[3][2] = fma2(wb2.y, xd2, acc3p[3][2]);
            acc3p[3][3] = fma2(wb2.y, xd3, acc3p[3][3]);
        }

        #pragma unroll
        for (int p = 0; p < 4; p++) {
            float e[2][4];
            #pragma unroll
            for (int q = 0; q < 4; q++) unpack2(acc3p[p][q], e[0][q], e[1][q]);
            #pragma unroll
            for (int k = 0; k < 2; k++) {
                int gc = g * 128 + ocb + p * 2 + k;
                float sc = g3[gc] * rsqrtf(v3[gc] + EPSV);
                float bi = b3[gc] - m3[gc] * sc;
                long idx = ((long)(b * CIN + gc) * H + h0 + r) * W + w0 + cst;
                float4 xv = *(const float4*)&x[idx];
                float4 v;
                v.x = fmaxf(e[k][0] * sc + bi + xv.x, 0.0f);
                v.y = fmaxf(e[k][1] * sc + bi + xv.y, 0.0f);
                v.z = fmaxf(e[k][2] * sc + bi + xv.z, 0.0f);
                v.w = fmaxf(e[k][3] * sc + bi + xv.w, 0.0f);
                *(float4*)&out[idx] = v;
            }
        }
    }
}

// ---------------------------------------------------------------------------
extern "C" void kernel_launch(void* const* d_in, const int* in_sizes, int n_in,
                              void* d_out, int out_size)
{
    const float* x    = (const float*)d_in[0];
    const float* mask = (const float*)d_in[1];
    const float* w1   = (const float*)d_in[2];
    const float* g1   = (const float*)d_in[3];
    const float* b1   = (const float*)d_in[4];
    const float* m1   = (const float*)d_in[5];
    const float* v1   = (const float*)d_in[6];
    const float* w2   = (const float*)d_in[7];
    const float* g2   = (const float*)d_in[8];
    const float* b2   = (const float*)d_in[9];
    const float* m2   = (const float*)d_in[10];
    const float* v2   = (const float*)d_in[11];
    const float* w3   = (const float*)d_in[12];
    const float* g3   = (const float*)d_in[13];
    const float* b3   = (const float*)d_in[14];
    const float* m3   = (const float*)d_in[15];
    const float* v3   = (const float*)d_in[16];
    float* out = (float*)d_out;

    cudaFuncSetAttribute(k23_fused, cudaFuncAttributeMaxDynamicSharedMemorySize, K23_SMEM);

    setup_tw<<<144, 256>>>(w1, w2, w3);
    dim3 grid1(49, 2, BATCH);
    k1_conv1<<<grid1, 256>>>(x, mask, g1, b1, m1, v1);
    dim3 grid2(49, GRP, BATCH);
    k23_fused<<<grid2, 128, K23_SMEM>>>(x, mask, g2, b2, m2, v2,
                                        g3, b3, m3, v3, out);
}

// round 12
// speedup vs baseline: 1.1096x; 1.1096x over previous
#include <cuda_runtime.h>

#define BATCH 16
#define CIN   512
#define MID   128
#define GRP   4
#define H     56
#define W     56
#define HW    (H*W)
#define MH    7
#define MW    7
#define EPSV  1e-5f

typedef unsigned long long ull;

__device__ __forceinline__ ull fma2(ull a, ull b, ull c) {
    ull d;
    asm("fma.rn.f32x2 %0, %1, %2, %3;" : "=l"(d) : "l"(a), "l"(b), "l"(c));
    return d;
}
__device__ __forceinline__ ull dup2(float v) {
    ull d;
    asm("mov.b64 %0, {%1, %1};" : "=l"(d) : "f"(v));
    return d;
}
__device__ __forceinline__ void unpack2(ull p, float& lo, float& hi) {
    asm("mov.b64 {%0, %1}, %2;" : "=f"(lo), "=f"(hi) : "l"(p));
}

// Scratch (device globals, no alloc).
__device__ float g_y1[BATCH * MID * HW];   // relu(bn1(conv1(x*m))) * m
// Pre-transposed weights:
__device__ float tw1[4 * 128 * 32];        // [g][ic][oc]
__device__ float tw2[4 * 32 * 9 * 32];     // [g][ic][tap][oc]
__device__ float tw3[4 * 32 * 128];        // [g][ic][oc]

__global__ void setup_tw(const float* __restrict__ w1,
                         const float* __restrict__ w2,
                         const float* __restrict__ w3)
{
    int i = blockIdx.x * 256 + threadIdx.x;
    if (i < 16384) {                       // tw1[g][ic][oc32]
        int g = i >> 12, r = i & 4095, ic = r >> 5, oc = r & 31;
        tw1[i] = w1[(g * 32 + oc) * 128 + ic];
    }
    if (i < 36864) {                       // tw2[g][ic][kk][oc32]
        int g = i / 9216, r = i % 9216, ic = r / 288, r2 = r % 288;
        int kk = r2 >> 5, oc = r2 & 31;
        tw2[i] = w2[(g * 32 + oc) * 288 + ic * 9 + kk];
    }
    if (i < 16384) {                       // tw3[g][ic][oc128]
        int g = i >> 12, r = i & 4095, ic = r >> 7, oc = r & 127;
        tw3[i] = w3[(g * 128 + oc) * 32 + ic];
    }
}

// ---------------------------------------------------------------------------
// Kernel 1: 1x1 grouped conv (512->128) + BN + ReLU (+mask), 8x8 tile.
// CTA = (tile, group-pair, batch), 256 thr. Thread = 4px x 4oc. f32x2.
// (unchanged from R10 — measured component)
// ---------------------------------------------------------------------------
__global__ __launch_bounds__(256, 3) void k1_conv1(
    const float* __restrict__ x, const float* __restrict__ mask,
    const float* __restrict__ g1, const float* __restrict__ b1,
    const float* __restrict__ m1, const float* __restrict__ v1)
{
    const int bh = blockIdx.x / 7, bw = blockIdx.x % 7;
    const int gp = blockIdx.y, b = blockIdx.z;      // group pair (0/1)
    const int h0 = bh * 8, w0 = bw * 8;
    const int t = threadIdx.x;
    const int ocq = t >> 4;            // [0,16): 4-oc slice within 64 oc
    const int pxq = t & 15;            // [0,16): 4-px quad
    const int r = pxq >> 1, cst = (pxq & 1) * 4;

    const float m0 = mask[((b * GRP + gp * 2 + 0) * MH + bh) * MW + bw];
    const float m1v = mask[((b * GRP + gp * 2 + 1) * MH + bh) * MW + bw];

    if (m0 == 0.0f && m1v == 0.0f) {
        const float4 z = make_float4(0.f, 0.f, 0.f, 0.f);
        #pragma unroll
        for (int k = 0; k < 4; k++) {
            int gc = gp * 64 + ocq * 4 + k;
            *(float4*)&g_y1[((b * MID + gc) * H + h0 + r) * W + w0 + cst] = z;
        }
        return;
    }

    __shared__ float  w_s[128][68];     // [ic][oc 0..63], pad 68
    __shared__ float4 x_s[2][32][16];   // [grp][ic-in-chunk][pxq]
    float4* xlin = &x_s[0][0][0];       // linear: idx == loader id

    {
        const float4* src = (const float4*)(tw1 + gp * 2 * 4096);
        float4* dst = (float4*)&w_s[0][0];          // row stride 17 float4
        #pragma unroll
        for (int j = 0; j < 8; j++) {
            int i = t + j * 256;
            int gg = i >> 10, rem = i & 1023;
            int ic = rem >> 3, oc4 = rem & 7;
            dst[ic * 17 + gg * 8 + oc4] = src[i];
        }
    }

    const int myg = ocq >> 3;               // warp-uniform group
    const bool active = (myg ? m1v : m0) != 0.0f;

    const float* xbase = x + (long)(b * CIN + gp * 2 * 128) * HW;
    long off[4];
    unsigned lmask = 0;
    #pragma unroll
    for (int j = 0; j < 4; j++) {
        int id = t + j * 256;
        int gg = id >> 9, ic = (id >> 4) & 31, p4 = id & 15;
        int rr = p4 >> 1, c2 = (p4 & 1) * 4;
        off[j] = ((long)(gg * 128 + ic) * H + h0 + rr) * W + w0 + c2;
        if ((gg ? m1v : m0) != 0.0f) lmask |= (1u << j);
    }

    #pragma unroll
    for (int j = 0; j < 4; j++) {
        float4 v = make_float4(0.f, 0.f, 0.f, 0.f);
        if (lmask & (1u << j)) v = *(const float4*)(xbase + off[j]);
        xlin[t + j * 256] = v;
    }
    __syncthreads();

    ull acc[4][2];
    #pragma unroll
    for (int k = 0; k < 4; k++) { acc[k][0] = 0ull; acc[k][1] = 0ull; }

    for (int cc = 0; cc < 4; cc++) {        // 4 chunks of 32 ic
        float4 pre[4];
        if (cc < 3) {
            #pragma unroll
            for (int j = 0; j < 4; j++) {
                pre[j] = make_float4(0.f, 0.f, 0.f, 0.f);
                if (lmask & (1u << j))
                    pre[j] = *(const float4*)(xbase + off[j] + (long)(cc + 1) * 32 * HW);
            }
        }
        if (active) {
            #pragma unroll
            for (int icc = 0; icc < 32; icc++) {
                ulonglong2 xp = *(const ulonglong2*)&x_s[myg][icc][pxq];
                float4 wv = *(const float4*)&w_s[cc * 32 + icc][ocq * 4];
                ull wd;
                wd = dup2(wv.x); acc[0][0] = fma2(wd, xp.x, acc[0][0]); acc[0][1] = fma2(wd, xp.y, acc[0][1]);
                wd = dup2(wv.y); acc[1][0] = fma2(wd, xp.x, acc[1][0]); acc[1][1] = fma2(wd, xp.y, acc[1][1]);
                wd = dup2(wv.z); acc[2][0] = fma2(wd, xp.x, acc[2][0]); acc[2][1] = fma2(wd, xp.y, acc[2][1]);
                wd = dup2(wv.w); acc[3][0] = fma2(wd, xp.x, acc[3][0]); acc[3][1] = fma2(wd, xp.y, acc[3][1]);
            }
        }
        if (cc < 3) {
            __syncthreads();
            #pragma unroll
            for (int j = 0; j < 4; j++)
                xlin[t + j * 256] = pre[j];
            __syncthreads();
        }
    }

    const float mymask = myg ? m1v : m0;
    #pragma unroll
    for (int k = 0; k < 4; k++) {
        int gc = gp * 64 + ocq * 4 + k;
        float sc = g1[gc] * rsqrtf(v1[gc] + EPSV);
        float bi = b1[gc] - m1[gc] * sc;
        float4 v = make_float4(0.f, 0.f, 0.f, 0.f);
        if (mymask != 0.0f) {
            float a0, a1, a2, a3;
            unpack2(acc[k][0], a0, a1);
            unpack2(acc[k][1], a2, a3);
            v.x = fmaxf(a0 * sc + bi, 0.0f);
            v.y = fmaxf(a1 * sc + bi, 0.0f);
            v.z = fmaxf(a2 * sc + bi, 0.0f);
            v.w = fmaxf(a3 * sc + bi, 0.0f);
        }
        *(float4*)&g_y1[((b * MID + gc) * H + h0 + r) * W + w0 + cst] = v;
    }
}

// ---------------------------------------------------------------------------
// Fused Kernel 2+3, BATCH-PAIRED: CTA = (tile, group, z) handles batches
// z and z+8. 256 thr, thread = 4px x 2oc (conv2, f32x2 oc-pair) and
// 4px x 8oc (conv3). Weights loaded ONCE per CTA, shared by both batches;
// w-LDS in conv2 inner loop shared across batches.
// smem (floats): A0 [0,3840)      halo b0 [32][120] -> later y2 b0 [32][64]
//                A1 [3840,7680)   halo b1            -> later y2 b1
//                B  [7680,12288)  w2 phase slab [16][9][32]
//                C  [12288,16384) w3 [32][128]
// ---------------------------------------------------------------------------
#define SM_A0 0
#define SM_A1 3840
#define SM_B  7680
#define SM_C  12288
#define K23_SMEM (16384 * 4)

__global__ __launch_bounds__(256, 3) void k23_fused(
    const float* __restrict__ x, const float* __restrict__ mask,
    const float* __restrict__ g2, const float* __restrict__ b2,
    const float* __restrict__ m2, const float* __restrict__ v2,
    const float* __restrict__ g3, const float* __restrict__ b3,
    const float* __restrict__ m3, const float* __restrict__ v3,
    float* __restrict__ out)
{
    const int bh = blockIdx.x / 7, bw = blockIdx.x % 7;
    const int g = blockIdx.y;
    const int b0 = blockIdx.z, b1 = blockIdx.z + 8;
    const int h0 = bh * 8, w0 = bw * 8;
    const int t = threadIdx.x;
    const int pxq = t & 15;                 // 4-px quad
    const int ocq2 = t >> 4;                // conv2: 2 oc; conv3: 8 oc
    const int r = pxq >> 1, cst = (pxq & 1) * 4;

    const float ma = mask[((b0 * GRP + g) * MH + bh) * MW + bw];
    const float mb = mask[((b1 * GRP + g) * MH + bh) * MW + bw];
    const bool act0 = (ma != 0.0f), act1 = (mb != 0.0f);

    // cheap residual path for masked batches (issued early, overlaps loads)
    #pragma unroll
    for (int bt = 0; bt < 2; bt++) {
        if (bt ? act1 : act0) continue;
        int b = bt ? b1 : b0;
        #pragma unroll
        for (int k = 0; k < 8; k++) {
            int gc = g * 128 + ocq2 * 8 + k;
            float sc = g3[gc] * rsqrtf(v3[gc] + EPSV);
            float bi = b3[gc] - m3[gc] * sc;
            long idx = ((long)(b * CIN + gc) * H + h0 + r) * W + w0 + cst;
            float4 xv = *(const float4*)&x[idx];
            float4 v;
            v.x = fmaxf(bi + xv.x, 0.0f);
            v.y = fmaxf(bi + xv.y, 0.0f);
            v.z = fmaxf(bi + xv.z, 0.0f);
            v.w = fmaxf(bi + xv.w, 0.0f);
            *(float4*)&out[idx] = v;
        }
    }
    if (!act0 && !act1) return;

    extern __shared__ float sm[];

    // halo loads (only for active batches)
    #pragma unroll
    for (int bt = 0; bt < 2; bt++) {
        if (!(bt ? act1 : act0)) continue;
        int b = bt ? b1 : b0;
        float* A = sm + (bt ? SM_A1 : SM_A0);
        for (int i = t; i < 32 * 100; i += 256) {
            int ic = i / 100, p = i % 100;
            int pr = p / 10, pc = p % 10;
            int rr = h0 + pr - 1, c2 = w0 + pc - 1;
            float v = 0.0f;
            if (rr >= 0 && rr < H && c2 >= 0 && c2 < W)
                v = g_y1[((b * MID + g * 32 + ic) * H + rr) * W + c2];
            A[ic * 120 + pr * 12 + pc] = v;
        }
    }
    // w3 slab
    {
        const float4* src = (const float4*)(tw3 + g * 4096);
        float4* dst = (float4*)(sm + SM_C);
        #pragma unroll
        for (int j = 0; j < 4; j++)
            dst[t + j * 256] = src[t + j * 256];
    }
    // w2 phase 0
    {
        const float4* src = (const float4*)(tw2 + g * 9216);
        float4* dst = (float4*)(sm + SM_B);
        #pragma unroll
        for (int j = 0; j < 5; j++) {
            int i = t + j * 256;
            if (i < 1152) dst[i] = src[i];
        }
    }
    __syncthreads();

    // ---- conv2 for both batches, w regs shared ----
    ull acc2p[2][4];                        // [batch][px], oc-pair packed
    #pragma unroll
    for (int bt = 0; bt < 2; bt++)
        #pragma unroll
        for (int q = 0; q < 4; q++) acc2p[bt][q] = 0ull;

    for (int ph = 0; ph < 2; ph++) {
        if (ph) {
            __syncthreads();
            const float4* src = (const float4*)(tw2 + g * 9216 + 4608);
            float4* dst = (float4*)(sm + SM_B);
            #pragma unroll
            for (int j = 0; j < 5; j++) {
                int i = t + j * 256;
                if (i < 1152) dst[i] = src[i];
            }
            __syncthreads();
        }
        #pragma unroll 2
        for (int icc = 0; icc < 16; icc++) {
            int ic = ph * 16 + icc;
            const float* wb = sm + SM_B + icc * 288;
            ull wv[9];
            #pragma unroll
            for (int kk = 0; kk < 9; kk++)
                wv[kk] = *(const ull*)&wb[kk * 32 + ocq2 * 2];
            #pragma unroll
            for (int bt = 0; bt < 2; bt++) {
                if (!(bt ? act1 : act0)) continue;
                const float* hb = sm + (bt ? SM_A1 : SM_A0) + ic * 120;
                #pragma unroll
                for (int kr = 0; kr < 3; kr++) {
                    float4 a = *(const float4*)&hb[(r + kr) * 12 + cst];
                    float2 bq = *(const float2*)&hb[(r + kr) * 12 + cst + 4];
                    ull xd[6];
                    xd[0] = dup2(a.x); xd[1] = dup2(a.y); xd[2] = dup2(a.z);
                    xd[3] = dup2(a.w); xd[4] = dup2(bq.x); xd[5] = dup2(bq.y);
                    #pragma unroll
                    for (int kc = 0; kc < 3; kc++) {
                        acc2p[bt][0] = fma2(wv[kr * 3 + kc], xd[kc + 0], acc2p[bt][0]);
                        acc2p[bt][1] = fma2(wv[kr * 3 + kc], xd[kc + 1], acc2p[bt][1]);
                        acc2p[bt][2] = fma2(wv[kr * 3 + kc], xd[kc + 2], acc2p[bt][2]);
                        acc2p[bt][3] = fma2(wv[kr * 3 + kc], xd[kc + 3], acc2p[bt][3]);
                    }
                }
            }
        }
    }

    // halo reads done -> write y2 tiles into A regions
    __syncthreads();
    #pragma unroll
    for (int bt = 0; bt < 2; bt++) {
        if (!(bt ? act1 : act0)) continue;
        float e0[4], e1[4];
        #pragma unroll
        for (int q = 0; q < 4; q++) unpack2(acc2p[bt][q], e0[q], e1[q]);
        float* A = sm + (bt ? SM_A1 : SM_A0);
        #pragma unroll
        for (int k = 0; k < 2; k++) {
            int gc = g * 32 + ocq2 * 2 + k;
            float sc = g2[gc] * rsqrtf(v2[gc] + EPSV);
            float bi = b2[gc] - m2[gc] * sc;
            const float* av = k ? e1 : e0;
            float4 v;
            v.x = fmaxf(av[0] * sc + bi, 0.0f);
            v.y = fmaxf(av[1] * sc + bi, 0.0f);
            v.z = fmaxf(av[2] * sc + bi, 0.0f);
            v.w = fmaxf(av[3] * sc + bi, 0.0f);
            *(float4*)&A[(ocq2 * 2 + k) * 64 + pxq * 4] = v;
        }
    }
    __syncthreads();

    // ---- conv3 per batch (sequential) ----
    const float* w3s = sm + SM_C;
    #pragma unroll
    for (int bt = 0; bt < 2; bt++) {
        if (!(bt ? act1 : act0)) continue;
        int b = bt ? b1 : b0;
        const float* A = sm + (bt ? SM_A1 : SM_A0);

        ull acc3p[4][4];                    // [ocpair][px]
        #pragma unroll
        for (int p = 0; p < 4; p++)
            #pragma unroll
            for (int q = 0; q < 4; q++) acc3p[p][q] = 0ull;

        #pragma unroll 4
        for (int ic = 0; ic < 32; ic++) {
            float4 xv = *(const float4*)&A[ic * 64 + pxq * 4];
            ull xd0 = dup2(xv.x), xd1 = dup2(xv.y), xd2 = dup2(xv.z), xd3 = dup2(xv.w);
            const float* wr = &w3s[ic * 128 + ocq2 * 8];
            ulonglong2 wa = *(const ulonglong2*)wr;
            ulonglong2 wb2 = *(const ulonglong2*)(wr + 4);
            acc3p[0][0] = fma2(wa.x, xd0, acc3p[0][0]);
            acc3p[0][1] = fma2(wa.x, xd1, acc3p[0][1]);
            acc3p[0][2] = fma2(wa.x, xd2, acc3p[0][2]);
            acc3p[0][3] = fma2(wa.x, xd3, acc3p[0][3]);
            acc3p[1][0] = fma2(wa.y, xd0, acc3p[1][0]);
            acc3p[1][1] = fma2(wa.y, xd1, acc3p[1][1]);
            acc3p[1][2] = fma2(wa.y, xd2, acc3p[1][2]);
            acc3p[1][3] = fma2(wa.y, xd3, acc3p[1][3]);
            acc3p[2][0] = fma2(wb2.x, xd0, acc3p[2][0]);
            acc3p[2][1] = fma2(wb2.x, xd1, acc3p[2][1]);
            acc3p[2][2] = fma2(wb2.x, xd2, acc3p[2][2]);
            acc3p[2][3] = fma2(wb2.x, xd3, acc3p[2][3]);
            acc3p[3][0] = fma2(wb2.y, xd0, acc3p[3][0]);
            acc3p[3][1] = fma2(wb2.y, xd1, acc3p[3][1]);
            acc3p[3][2] = fma2(wb2.y, xd2, acc3p[3][2]);
            acc3p[3][3] = fma2(wb2.y, xd3, acc3p[3][3]);
        }

        #pragma unroll
        for (int p = 0; p < 4; p++) {
            float e[2][4];
            #pragma unroll
            for (int q = 0; q < 4; q++) unpack2(acc3p[p][q], e[0][q], e[1][q]);
            #pragma unroll
            for (int k = 0; k < 2; k++) {
                int gc = g * 128 + ocq2 * 8 + p * 2 + k;
                float sc = g3[gc] * rsqrtf(v3[gc] + EPSV);
                float bi = b3[gc] - m3[gc] * sc;
                long idx = ((long)(b * CIN + gc) * H + h0 + r) * W + w0 + cst;
                float4 xv = *(const float4*)&x[idx];
                float4 v;
                v.x = fmaxf(e[k][0] * sc + bi + xv.x, 0.0f);
                v.y = fmaxf(e[k][1] * sc + bi + xv.y, 0.0f);
                v.z = fmaxf(e[k][2] * sc + bi + xv.z, 0.0f);
                v.w = fmaxf(e[k][3] * sc + bi + xv.w, 0.0f);
                *(float4*)&out[idx] = v;
            }
        }
    }
}

// ---------------------------------------------------------------------------
extern "C" void kernel_launch(void* const* d_in, const int* in_sizes, int n_in,
                              void* d_out, int out_size)
{
    const float* x    = (const float*)d_in[0];
    const float* mask = (const float*)d_in[1];
    const float* w1   = (const float*)d_in[2];
    const float* g1   = (const float*)d_in[3];
    const float* b1   = (const float*)d_in[4];
    const float* m1   = (const float*)d_in[5];
    const float* v1   = (const float*)d_in[6];
    const float* w2   = (const float*)d_in[7];
    const float* g2   = (const float*)d_in[8];
    const float* b2   = (const float*)d_in[9];
    const float* m2   = (const float*)d_in[10];
    const float* v2   = (const float*)d_in[11];
    const float* w3   = (const float*)d_in[12];
    const float* g3   = (const float*)d_in[13];
    const float* b3   = (const float*)d_in[14];
    const float* m3   = (const float*)d_in[15];
    const float* v3   = (const float*)d_in[16];
    float* out = (float*)d_out;

    cudaFuncSetAttribute(k23_fused, cudaFuncAttributeMaxDynamicSharedMemorySize, K23_SMEM);

    setup_tw<<<144, 256>>>(w1, w2, w3);
    dim3 grid1(49, 2, BATCH);
    k1_conv1<<<grid1, 256>>>(x, mask, g1, b1, m1, v1);
    dim3 grid2(49, GRP, 8);
    k23_fused<<<grid2, 256, K23_SMEM>>>(x, mask, g2, b2, m2, v2,
                                        g3, b3, m3, v3, out);
}